// round 2
// baseline (speedup 1.0000x reference)
#include <cuda_runtime.h>

// Problem constants
#define IMGS 64
#define W    512
#define H    512
#define RAD  15           // box radius (kernel 31)
#define STRIP 128         // rows per block
#define NSTRIP (H / STRIP)
#define INV_KK (1.0f / 961.0f)

// Per-image accumulators: [img][0]=wsum, [img][1]=w*bce sum, [img][2]=w*iou sum
__device__ float g_acc[IMGS * 3];

__global__ void init_acc_kernel() {
    int i = blockIdx.x * blockDim.x + threadIdx.x;
    if (i < IMGS * 3) g_acc[i] = 0.0f;
}

__device__ __forceinline__ void pixel_math(float box, float m, float p,
                                           float& aw, float& ab, float& ai) {
    float avg = box * INV_KK;
    float w   = 1.0f + 5.0f * fabsf(avg - m);

    float ap = fabsf(p);
    float e  = __expf(-ap);            // exp(-|p|), in (0,1]
    float r  = __fdividef(1.0f, 1.0f + e);
    float lg = -__logf(r);             // log(1+e^-|p|) = -log(r)
    float bce = fmaxf(p, 0.0f) - p * m + lg;

    float s = (p >= 0.0f) ? r : e * r; // sigmoid(p), stable both signs
    float inter = s * m;
    float uni   = s + m;
    float iou = 1.0f - __fdividef(inter + 1.0f, uni - inter + 1.0f);

    aw += w;
    ab += w * bce;
    ai += w * iou;
}

__global__ __launch_bounds__(512)
void fused_kernel(const float* __restrict__ pred,
                  const float* __restrict__ mask) {
    __shared__ float sP[4][W];             // per-row column prefix sums
    __shared__ float wsum[4][16];          // per-warp scan totals
    __shared__ float wex[4][16];           // per-warp exclusive offsets
    __shared__ float red[3][16];

    const int x    = threadIdx.x;          // column, 0..511
    const int lane = x & 31;
    const int wid  = x >> 5;               // 0..15
    const int img  = blockIdx.y;
    const int y0   = blockIdx.x * STRIP;

    const float* M  = mask + (size_t)img * W * H;
    const float* Pr = pred + (size_t)img * W * H;

    // ---- init vertical column sum over rows [y0-15, y0+15] (clamped) ----
    float cs = 0.0f;
    #pragma unroll 1
    for (int r = y0 - RAD; r <= y0 + RAD; ++r) {
        if (r >= 0) cs += M[r * W + x];    // r <= 399 < 512 always (max y0=384)
    }

    float aw = 0.0f, ab = 0.0f, ai = 0.0f;

    // ---- march down the strip, FOUR rows per scan iteration ----
    #pragma unroll 1
    for (int y = y0; y < y0 + STRIP; y += 4) {
        // v[k] = vertical column-sum for row y+k; roll cs forward 4 rows
        float t0, t1, t2, t3;
        t0 = cs;
        #pragma unroll
        for (int k = 1; k <= 4; ++k) {
            int ra = y + k + RAD;          // row entering window of (y+k)
            int rs = y + k - 16;           // row leaving
            float add = (ra < H)  ? M[ra * W + x] : 0.0f;
            float sub = (rs >= 0) ? M[rs * W + x] : 0.0f;
            cs += add - sub;
            if (k == 1) t1 = cs;
            else if (k == 2) t2 = cs;
            else if (k == 3) t3 = cs;
        }
        // after k=4, cs holds row y+4's window (next iteration's t0)

        // warp-level inclusive scans, 4 rows interleaved for ILP
        #pragma unroll
        for (int off = 1; off < 32; off <<= 1) {
            float u0 = __shfl_up_sync(0xffffffffu, t0, off);
            float u1 = __shfl_up_sync(0xffffffffu, t1, off);
            float u2 = __shfl_up_sync(0xffffffffu, t2, off);
            float u3 = __shfl_up_sync(0xffffffffu, t3, off);
            if (lane >= off) { t0 += u0; t1 += u1; t2 += u2; t3 += u3; }
        }
        if (lane == 31) {
            wsum[0][wid] = t0; wsum[1][wid] = t1;
            wsum[2][wid] = t2; wsum[3][wid] = t3;
        }
        __syncthreads();

        // warps 0,1: scan the 16 warp-sums for rows (2*wid, 2*wid+1)
        if (wid < 2) {
            int row = 2 * wid + (lane >> 4);       // 0..3
            float v   = wsum[row][lane & 15];
            float inc = v;
            #pragma unroll
            for (int off = 1; off < 16; off <<= 1) {
                float u = __shfl_up_sync(0xffffffffu, inc, off);
                if ((lane & 15) >= off) inc += u;
            }
            wex[row][lane & 15] = inc - v;         // exclusive offset
        }
        __syncthreads();

        sP[0][x] = t0 + wex[0][wid];
        sP[1][x] = t1 + wex[1][wid];
        sP[2][x] = t2 + wex[2][wid];
        sP[3][x] = t3 + wex[3][wid];
        __syncthreads();

        // 2D box sum = P[min(x+15,511)] - P[x-16]
        int hi = (x + RAD < W) ? (x + RAD) : (W - 1);
        float b0 = sP[0][hi], b1 = sP[1][hi], b2 = sP[2][hi], b3 = sP[3][hi];
        if (x >= 16) {
            b0 -= sP[0][x - 16]; b1 -= sP[1][x - 16];
            b2 -= sP[2][x - 16]; b3 -= sP[3][x - 16];
        }

        // elementwise math for rows y..y+3 (M rows are L1-resident)
        pixel_math(b0, M[(y + 0) * W + x], Pr[(y + 0) * W + x], aw, ab, ai);
        pixel_math(b1, M[(y + 1) * W + x], Pr[(y + 1) * W + x], aw, ab, ai);
        pixel_math(b2, M[(y + 2) * W + x], Pr[(y + 2) * W + x], aw, ab, ai);
        pixel_math(b3, M[(y + 3) * W + x], Pr[(y + 3) * W + x], aw, ab, ai);

        __syncthreads();  // protect sP/wsum before next iteration overwrites
    }

    // ---- block reduction of (aw, ab, ai) ----
    #pragma unroll
    for (int off = 16; off > 0; off >>= 1) {
        aw += __shfl_down_sync(0xffffffffu, aw, off);
        ab += __shfl_down_sync(0xffffffffu, ab, off);
        ai += __shfl_down_sync(0xffffffffu, ai, off);
    }
    if (lane == 0) { red[0][wid] = aw; red[1][wid] = ab; red[2][wid] = ai; }
    __syncthreads();
    if (wid == 0) {
        float a = (lane < 16) ? red[0][lane] : 0.0f;
        float b = (lane < 16) ? red[1][lane] : 0.0f;
        float c = (lane < 16) ? red[2][lane] : 0.0f;
        #pragma unroll
        for (int off = 8; off > 0; off >>= 1) {
            a += __shfl_down_sync(0xffffffffu, a, off);
            b += __shfl_down_sync(0xffffffffu, b, off);
            c += __shfl_down_sync(0xffffffffu, c, off);
        }
        if (lane == 0) {
            atomicAdd(&g_acc[img * 3 + 0], a);
            atomicAdd(&g_acc[img * 3 + 1], b);
            atomicAdd(&g_acc[img * 3 + 2], c);
        }
    }
}

__global__ void finalize_kernel(float* __restrict__ out) {
    __shared__ float sh[64];
    int i = threadIdx.x;                   // 64 threads
    float w = g_acc[i * 3 + 0];
    float b = g_acc[i * 3 + 1];
    float u = g_acc[i * 3 + 2];
    sh[i] = (b + u) / w;                   // wbce_i + wiou_i
    __syncthreads();
    #pragma unroll
    for (int off = 32; off > 0; off >>= 1) {
        if (i < off) sh[i] += sh[i + off];
        __syncthreads();
    }
    if (i == 0) out[0] = sh[0] * (1.0f / 64.0f);
}

extern "C" void kernel_launch(void* const* d_in, const int* in_sizes, int n_in,
                              void* d_out, int out_size) {
    const float* pred = (const float*)d_in[0];
    const float* mask = (const float*)d_in[1];
    float* out = (float*)d_out;

    init_acc_kernel<<<1, IMGS * 3>>>();
    dim3 grid(NSTRIP, IMGS);              // 4 x 64 = 256 blocks
    fused_kernel<<<grid, W>>>(pred, mask);
    finalize_kernel<<<1, 64>>>(out);
}

// round 5
// speedup vs baseline: 1.4243x; 1.4243x over previous
#include <cuda_runtime.h>

// Problem constants
#define IMGS 64
#define W    512
#define H    512
#define RAD  15            // box radius (kernel 31)
#define STRIP 64           // rows per block
#define NSTRIP (H / STRIP) // 8
#define NBLK (NSTRIP * IMGS) // 512 blocks
#define INV_KK (1.0f / 961.0f)

// Per-block partials [blk][0]=wsum [1]=w*bce [2]=w*iou, + completion counter
__device__ float g_part[NBLK * 3];
__device__ int   g_count = 0;

__device__ __forceinline__ void pixel_math(float box, float m, float p,
                                           float& aw, float& ab, float& ai) {
    float avg = box * INV_KK;
    float w   = 1.0f + 5.0f * fabsf(avg - m);

    float ap = fabsf(p);
    float e  = __expf(-ap);            // exp(-|p|)
    float r  = __fdividef(1.0f, 1.0f + e);
    float lg = -__logf(r);             // log1p(exp(-|p|))
    float bce = fmaxf(p, 0.0f) - p * m + lg;

    float s = (p >= 0.0f) ? r : e * r; // sigmoid(p), stable
    float inter = s * m;
    float uni   = s + m;
    float iou = 1.0f - __fdividef(inter + 1.0f, uni - inter + 1.0f);

    aw += w;
    ab += w * bce;
    ai += w * iou;
}

__global__ __launch_bounds__(512, 2)
void fused_kernel(const float* __restrict__ pred,
                  const float* __restrict__ mask,
                  float* __restrict__ out) {
    // [buf][row][warp+1][lane] warp-prefix exchange; slots 0 and 17 are
    // zero-padded "virtual warps" so edge clamping falls out of the formula.
    __shared__ float sT[2][4][18][32];
    __shared__ float red[3][16];
    __shared__ float fin[64];
    __shared__ int   s_last;

    const int x    = threadIdx.x;      // column, 0..511
    const int lane = x & 31;
    const int wid  = x >> 5;           // 0..15
    const int img  = blockIdx.y;
    const int strip = blockIdx.x;
    const int y0   = strip * STRIP;

    const float* M  = mask + (size_t)img * W * H;
    const float* Pr = pred + (size_t)img * W * H;

    // zero the 512 virtual-warp slots (exactly one per thread)
    {
        int buf = x >> 8, rem = x & 255;
        int row = rem >> 6, side = (rem >> 5) & 1, l = rem & 31;
        sT[buf][row][side ? 17 : 0][l] = 0.0f;
    }
    // (first __syncthreads inside the loop publishes these before any read)

    // ---- init vertical column sum over rows [y0-15, y0+15] (clamped) ----
    float cs = 0.0f;
    #pragma unroll 1
    for (int r = y0 - RAD; r <= y0 + RAD; ++r) {
        if (r >= 0) cs += M[r * W + x];    // r <= 463 < 512 always
    }

    float aw = 0.0f, ab = 0.0f, ai = 0.0f;

    // ---- 4 rows per iteration, ONE barrier per iteration ----
    #pragma unroll 1
    for (int it = 0; it < STRIP / 4; ++it) {
        const int y   = y0 + it * 4;
        const int buf = it & 1;

        // rolling vertical sums for rows y..y+3
        float t0 = cs, t1, t2, t3;
        {
            float a1 = (y + 16 < H) ? M[(y + 16) * W + x] : 0.0f;
            float s1 = (y - 15 >= 0) ? M[(y - 15) * W + x] : 0.0f;
            cs += a1 - s1; t1 = cs;
            float a2 = (y + 17 < H) ? M[(y + 17) * W + x] : 0.0f;
            float s2 = (y - 14 >= 0) ? M[(y - 14) * W + x] : 0.0f;
            cs += a2 - s2; t2 = cs;
            float a3 = (y + 18 < H) ? M[(y + 18) * W + x] : 0.0f;
            float s3 = (y - 13 >= 0) ? M[(y - 13) * W + x] : 0.0f;
            cs += a3 - s3; t3 = cs;
            float a4 = (y + 19 < H) ? M[(y + 19) * W + x] : 0.0f;
            float s4 = (y - 12 >= 0) ? M[(y - 12) * W + x] : 0.0f;
            cs += a4 - s4;                 // window of row y+4 (next iter t0)
        }

        // warp-local inclusive scans, 4 rows interleaved
        #pragma unroll
        for (int off = 1; off < 32; off <<= 1) {
            float u0 = __shfl_up_sync(0xffffffffu, t0, off);
            float u1 = __shfl_up_sync(0xffffffffu, t1, off);
            float u2 = __shfl_up_sync(0xffffffffu, t2, off);
            float u3 = __shfl_up_sync(0xffffffffu, t3, off);
            if (lane >= off) { t0 += u0; t1 += u1; t2 += u2; t3 += u3; }
        }
        sT[buf][0][wid + 1][lane] = t0;
        sT[buf][1][wid + 1][lane] = t1;
        sT[buf][2][wid + 1][lane] = t2;
        sT[buf][3][wid + 1][lane] = t3;
        __syncthreads();

        // own-warp values: t(l+15) for l<=15, t(l-16) for l>=16 (SHFL.IDX)
        const int sidx = (lane <= 15) ? lane + 15 : lane - 16;
        float o0 = __shfl_sync(0xffffffffu, t0, sidx);
        float o1 = __shfl_sync(0xffffffffu, t1, sidx);
        float o2 = __shfl_sync(0xffffffffu, t2, sidx);
        float o3 = __shfl_sync(0xffffffffu, t3, sidx);
        float T0 = __shfl_sync(0xffffffffu, t0, 31);
        float T1 = __shfl_sync(0xffffffffu, t1, 31);
        float T2 = __shfl_sync(0xffffffffu, t2, 31);
        float T3 = __shfl_sync(0xffffffffu, t3, 31);

        float b0, b1, b2, b3;
        if (lane <= 15) {
            // box = S_{w-1} - t_{w-1}(l+16) + t_w(l+15)
            float Tp0 = sT[buf][0][wid][31], n0 = sT[buf][0][wid][lane + 16];
            float Tp1 = sT[buf][1][wid][31], n1 = sT[buf][1][wid][lane + 16];
            float Tp2 = sT[buf][2][wid][31], n2 = sT[buf][2][wid][lane + 16];
            float Tp3 = sT[buf][3][wid][31], n3 = sT[buf][3][wid][lane + 16];
            b0 = Tp0 - n0 + o0;
            b1 = Tp1 - n1 + o1;
            b2 = Tp2 - n2 + o2;
            b3 = Tp3 - n3 + o3;
        } else {
            // box = S_w - t_w(l-16) + t_{w+1}(l-17)   [last term 0 at l==16]
            float n0 = 0.f, n1 = 0.f, n2 = 0.f, n3 = 0.f;
            if (lane >= 17) {
                n0 = sT[buf][0][wid + 2][lane - 17];
                n1 = sT[buf][1][wid + 2][lane - 17];
                n2 = sT[buf][2][wid + 2][lane - 17];
                n3 = sT[buf][3][wid + 2][lane - 17];
            }
            b0 = T0 - o0 + n0;
            b1 = T1 - o1 + n1;
            b2 = T2 - o2 + n2;
            b3 = T3 - o3 + n3;
        }

        // elementwise math for rows y..y+3; pred is single-use -> streaming
        // loads (__ldcs, evict-first) so the 31-row mask window stays in L1.
        pixel_math(b0, M[(y + 0) * W + x], __ldcs(&Pr[(y + 0) * W + x]), aw, ab, ai);
        pixel_math(b1, M[(y + 1) * W + x], __ldcs(&Pr[(y + 1) * W + x]), aw, ab, ai);
        pixel_math(b2, M[(y + 2) * W + x], __ldcs(&Pr[(y + 2) * W + x]), aw, ab, ai);
        pixel_math(b3, M[(y + 3) * W + x], __ldcs(&Pr[(y + 3) * W + x]), aw, ab, ai);
        // no trailing barrier: next iteration writes the other buffer;
        // its barrier orders the WAR correctly (double buffering).
    }

    // ---- block reduction of (aw, ab, ai) ----
    #pragma unroll
    for (int off = 16; off > 0; off >>= 1) {
        aw += __shfl_down_sync(0xffffffffu, aw, off);
        ab += __shfl_down_sync(0xffffffffu, ab, off);
        ai += __shfl_down_sync(0xffffffffu, ai, off);
    }
    if (lane == 0) { red[0][wid] = aw; red[1][wid] = ab; red[2][wid] = ai; }
    __syncthreads();
    if (wid == 0) {
        float a = (lane < 16) ? red[0][lane] : 0.0f;
        float b = (lane < 16) ? red[1][lane] : 0.0f;
        float c = (lane < 16) ? red[2][lane] : 0.0f;
        #pragma unroll
        for (int off = 8; off > 0; off >>= 1) {
            a += __shfl_down_sync(0xffffffffu, a, off);
            b += __shfl_down_sync(0xffffffffu, b, off);
            c += __shfl_down_sync(0xffffffffu, c, off);
        }
        if (lane == 0) {
            int bid = img * NSTRIP + strip;
            g_part[bid * 3 + 0] = a;
            g_part[bid * 3 + 1] = b;
            g_part[bid * 3 + 2] = c;
            __threadfence();
            int prev = atomicAdd(&g_count, 1);
            s_last = (prev == NBLK - 1) ? 1 : 0;
        }
    }
    __syncthreads();

    // ---- last finished block computes the final scalar ----
    if (s_last) {
        if (x < IMGS) {
            float w = 0.f, b = 0.f, u = 0.f;
            #pragma unroll
            for (int s = 0; s < NSTRIP; ++s) {
                int e = (x * NSTRIP + s) * 3;
                w += g_part[e + 0];
                b += g_part[e + 1];
                u += g_part[e + 2];
            }
            fin[x] = (b + u) / w;          // wbce_i + wiou_i
        }
        __syncthreads();
        #pragma unroll
        for (int off = 32; off > 0; off >>= 1) {
            if (x < off) fin[x] += fin[x + off];
            __syncthreads();
        }
        if (x == 0) {
            out[0] = fin[0] * (1.0f / 64.0f);
            g_count = 0;                   // reset for next graph replay
        }
    }
}

extern "C" void kernel_launch(void* const* d_in, const int* in_sizes, int n_in,
                              void* d_out, int out_size) {
    const float* pred = (const float*)d_in[0];
    const float* mask = (const float*)d_in[1];
    float* out = (float*)d_out;

    dim3 grid(NSTRIP, IMGS);              // 8 x 64 = 512 blocks
    fused_kernel<<<grid, W>>>(pred, mask, out);
}

// round 6
// speedup vs baseline: 1.9036x; 1.3366x over previous
#include <cuda_runtime.h>

// Problem constants
#define IMGS 64
#define W    512
#define H    512
#define Wq   (W / 4)        // 128 float4 quads per row
#define RAD  15             // box radius (kernel 31)
#define STRIP 64            // rows per block
#define NSTRIP (H / STRIP)  // 8
#define NBLK (NSTRIP * IMGS)
#define INV_KK (1.0f / 961.0f)

// Per-block partials [blk]{wsum, w*bce, w*iou} + completion counter
__device__ float g_part[NBLK * 3];
__device__ int   g_count = 0;

__device__ __forceinline__ void pixel_math(float box, float m, float p,
                                           float& aw, float& ab, float& ai) {
    float avg = box * INV_KK;
    float w   = 1.0f + 5.0f * fabsf(avg - m);

    float ap = fabsf(p);
    float e  = __expf(-ap);            // exp(-|p|)
    float r  = __fdividef(1.0f, 1.0f + e);
    float lg = -__logf(r);             // log1p(exp(-|p|))
    float bce = fmaxf(p, 0.0f) - p * m + lg;

    float s = (p >= 0.0f) ? r : e * r; // sigmoid(p), stable
    float inter = s * m;
    float uni   = s + m;
    float iou = 1.0f - __fdividef(inter + 1.0f, uni - inter + 1.0f);

    aw += w;
    ab += w * bce;
    ai += w * iou;
}

__global__ __launch_bounds__(512, 2)
void fused_kernel(const float* __restrict__ pred,
                  const float* __restrict__ mask,
                  float* __restrict__ out) {
    // Prefix rows: [buf][ty][ 16 left-pad(0) | 512 prefix | 16 right-pad(repl) ]
    __shared__ float sP[2][4][544];
    __shared__ float sWT[2][4][4];     // per-warp (128-col segment) totals
    __shared__ float offc[2][4][5];    // cumulative segment offsets (+1 overflow)
    __shared__ float red[3][16];
    __shared__ float fin[64];
    __shared__ int   s_last;

    const int tid  = threadIdx.x;
    const int lane = tid & 31;
    const int tx   = tid & 127;        // column-quad index (cols 4tx..4tx+3)
    const int ty   = tid >> 7;         // row-in-group 0..3
    const int wrow = tx >> 5;          // warp-within-row 0..3
    const int xb   = tx << 2;          // base column
    const int img  = blockIdx.y;
    const int y0   = blockIdx.x * STRIP;

    const float4* M4 = (const float4*)(mask + (size_t)img * W * H);
    const float4* P4 = (const float4*)(pred + (size_t)img * W * H);

    // zero the left pads once (one entry per thread, 128 entries)
    if (tid < 128) {
        int b = tid >> 6, r = (tid >> 4) & 3, i = tid & 15;
        sP[b][r][i] = 0.0f;
    }
    // (published by the first in-loop barrier)

    // ---- init vertical column sums for row y0+ty, window [y-15, y+15] ----
    float4 cs = make_float4(0.f, 0.f, 0.f, 0.f);
    #pragma unroll 1
    for (int r = y0 + ty - RAD; r <= y0 + ty + RAD; ++r) {
        if (r >= 0) {                  // r <= 466 < 512 always
            float4 v = M4[r * Wq + tx];
            cs.x += v.x; cs.y += v.y; cs.z += v.z; cs.w += v.w;
        }
    }

    float aw = 0.f, ab = 0.f, ai = 0.f;

    // ---- 4 rows (one per ty) per iteration ----
    #pragma unroll 1
    for (int it = 0; it < STRIP / 4; ++it) {
        const int y   = y0 + it * 4 + ty;   // this thread's row
        const int buf = it & 1;

        float4 t = cs;                       // colsum for row y

        // advance window by 4 rows: add y+16..y+19, sub y-15..y-12
        #pragma unroll
        for (int k = 0; k < 4; ++k) {
            int ra = y + 16 + k;
            int rs = y - RAD + k;
            float4 a = (ra < H)  ? M4[ra * Wq + tx] : make_float4(0.f,0.f,0.f,0.f);
            float4 s = (rs >= 0) ? M4[rs * Wq + tx] : make_float4(0.f,0.f,0.f,0.f);
            cs.x += a.x - s.x; cs.y += a.y - s.y;
            cs.z += a.z - s.z; cs.w += a.w - s.w;
        }

        // intra-thread prefix over the 4 owned columns
        float p0 = t.x, p1 = p0 + t.y, p2 = p1 + t.z, p3 = p2 + t.w;

        // warp-inclusive scan of thread sums (covers a 128-col segment)
        float sinc = p3;
        #pragma unroll
        for (int off = 1; off < 32; off <<= 1) {
            float u = __shfl_up_sync(0xffffffffu, sinc, off);
            if (lane >= off) sinc += u;
        }
        float e = sinc - p3;               // exclusive offset within segment

        *(float4*)&sP[buf][ty][16 + xb] = make_float4(e + p0, e + p1, e + p2, e + p3);
        if (lane == 31) sWT[buf][ty][wrow] = sinc;
        __syncthreads();

        // 16 threads: cumulative segment offsets + right-pad replication
        if (tid < 16) {
            int r = tid >> 2, w = tid & 3;
            float o = 0.f;
            #pragma unroll
            for (int w2 = 0; w2 < 3; ++w2)
                if (w2 < w) o += sWT[buf][r][w2];
            offc[buf][r][w] = o;
            if (w == 3) {
                offc[buf][r][4] = o;       // overflow zone uses segment-3 offset
                float last = sP[buf][r][527];   // segment-local prefix at x=511
                #pragma unroll
                for (int k = 0; k < 16; ++k) sP[buf][r][528 + k] = last;
            }
        }
        __syncthreads();

        // ---- consume: aligned quad reads of the prefix row ----
        // lo values  P(x-16), x=xb..xb+3  -> indices xb..xb+3        (aligned)
        // hi values  P(x+15)              -> indices 31+xb..34+xb
        //   = q1.w (28+xb..31+xb) and q2.xyz (32+xb..35+xb)          (aligned)
        float4 loq = *(const float4*)&sP[buf][ty][xb];
        float4 q1  = *(const float4*)&sP[buf][ty][28 + xb];
        float4 q2  = *(const float4*)&sP[buf][ty][32 + xb];

        float hiv[4] = { q1.w, q2.x, q2.y, q2.z };
        float lov[4] = { loq.x, loq.y, loq.z, loq.w };

        float4 m  = M4[y * Wq + tx];
        float4 pv = __ldcs(&P4[y * Wq + tx]);
        float mv[4] = { m.x, m.y, m.z, m.w };
        float pvv[4] = { pv.x, pv.y, pv.z, pv.w };

        #pragma unroll
        for (int i = 0; i < 4; ++i) {
            int x  = xb + i;
            int hw = (x + RAD) >> 7;               // 0..4 (pads -> 4)
            int lo = x - 16;
            int lw = (lo > 0 ? lo : 0) >> 7;       // pad zone -> 0 (offc[.][0]=0)
            float Ph = hiv[i] + offc[buf][ty][hw];
            float Pl = lov[i] + offc[buf][ty][lw];
            pixel_math(Ph - Pl, mv[i], pvv[i], aw, ab, ai);
        }
        // no trailing barrier: double buffer; next iteration's first barrier
        // orders the WAR on the other buffer.
    }

    // ---- block reduction of (aw, ab, ai) ----
    #pragma unroll
    for (int off = 16; off > 0; off >>= 1) {
        aw += __shfl_down_sync(0xffffffffu, aw, off);
        ab += __shfl_down_sync(0xffffffffu, ab, off);
        ai += __shfl_down_sync(0xffffffffu, ai, off);
    }
    const int wid = tid >> 5;
    if (lane == 0) { red[0][wid] = aw; red[1][wid] = ab; red[2][wid] = ai; }
    __syncthreads();
    if (wid == 0) {
        float a = (lane < 16) ? red[0][lane] : 0.0f;
        float b = (lane < 16) ? red[1][lane] : 0.0f;
        float c = (lane < 16) ? red[2][lane] : 0.0f;
        #pragma unroll
        for (int off = 8; off > 0; off >>= 1) {
            a += __shfl_down_sync(0xffffffffu, a, off);
            b += __shfl_down_sync(0xffffffffu, b, off);
            c += __shfl_down_sync(0xffffffffu, c, off);
        }
        if (lane == 0) {
            int bid = img * NSTRIP + blockIdx.x;
            g_part[bid * 3 + 0] = a;
            g_part[bid * 3 + 1] = b;
            g_part[bid * 3 + 2] = c;
            __threadfence();
            int prev = atomicAdd(&g_count, 1);
            s_last = (prev == NBLK - 1) ? 1 : 0;
        }
    }
    __syncthreads();

    // ---- last finished block computes the final scalar ----
    if (s_last) {
        if (tid < IMGS) {
            float w = 0.f, b = 0.f, u = 0.f;
            #pragma unroll
            for (int s = 0; s < NSTRIP; ++s) {
                int e2 = (tid * NSTRIP + s) * 3;
                w += g_part[e2 + 0];
                b += g_part[e2 + 1];
                u += g_part[e2 + 2];
            }
            fin[tid] = (b + u) / w;        // wbce_i + wiou_i
        }
        __syncthreads();
        #pragma unroll
        for (int off = 32; off > 0; off >>= 1) {
            if (tid < off) fin[tid] += fin[tid + off];
            __syncthreads();
        }
        if (tid == 0) {
            out[0] = fin[0] * (1.0f / 64.0f);
            g_count = 0;                   // reset for next graph replay
        }
    }
}

extern "C" void kernel_launch(void* const* d_in, const int* in_sizes, int n_in,
                              void* d_out, int out_size) {
    const float* pred = (const float*)d_in[0];
    const float* mask = (const float*)d_in[1];
    float* out = (float*)d_out;

    dim3 grid(NSTRIP, IMGS);              // 8 x 64 = 512 blocks
    fused_kernel<<<grid, W>>>(pred, mask, out);
}

// round 14
// speedup vs baseline: 2.0070x; 1.0543x over previous
#include <cuda_runtime.h>

#define IMGS 64
#define W    512
#define H    512
#define Wq   128            // float4 quads per row
#define RAD  15
#define STRIP 64
#define NSTRIP 8
#define NBLK (NSTRIP * IMGS)
#define INV_KK (1.0f / 961.0f)

__device__ float g_part[NBLK * 3];
__device__ int   g_count = 0;

// Collapsed math: e=exp(-|p|), a=1+e, c=(p>=0?1:e)  =>  sigmoid=c/a,
// log1p(exp(-|p|))=log(a),
// iou = 1 - (inter+1)/(uni-inter+1) = 1 - (c*m+a)/(c*(1-m)+a*(1+m)).
__device__ __forceinline__ void pixel_math(float box, float m, float p,
                                           float& aw, float& ab, float& ai) {
    float w   = fmaf(5.0f, fabsf(fmaf(box, INV_KK, -m)), 1.0f);
    float e   = __expf(-fabsf(p));
    float a   = 1.0f + e;
    float c   = (p >= 0.0f) ? 1.0f : e;
    float bce = fmaxf(p, 0.0f) + fmaf(-p, m, __logf(a));
    float g   = fmaf(m, a - c, a + c);       // c(1-m) + a(1+m)
    float num = fmaf(c, m, a);               // c*m + a
    float iou = 1.0f - __fdividef(num, g);
    aw += w;
    ab = fmaf(w, bce, ab);
    ai = fmaf(w, iou, ai);
}

template<bool CLAMP>
__device__ __forceinline__ void run_strip(
    const float4* __restrict__ M4, const float4* __restrict__ P4,
    int y0, int tx, int ty, int lane, int wrow, int xb,
    float (&sP)[8][544], float (&sWT)[8][4],
    float& aw, float& ab, float& ai)
{
    // ---- init vertical column sums for row y0+ty, window [y-15, y+15] ----
    float4 cs = make_float4(0.f, 0.f, 0.f, 0.f);
    #pragma unroll 1
    for (int r = y0 + ty - RAD; r <= y0 + ty + RAD; ++r) {
        if (!CLAMP || r >= 0) {            // r <= 478 < 512 always
            float4 v = M4[r * Wq + tx];
            cs.x += v.x; cs.y += v.y; cs.z += v.z; cs.w += v.w;
        }
    }

    // ---- 16 iterations, 4 rows each (one per ty) ----
    #pragma unroll 1
    for (int it = 0; it < STRIP / 4; ++it) {
        const int y  = y0 + it * 4 + ty;
        const int sb = ((it & 1) << 2) + ty;   // shared row: buf*4 + ty

        // hoisted consume-phase loads: independent of the scan below, so
        // issue them first and let ~2 barriers + scan hide their latency.
        const float4 m  = M4[y * Wq + tx];
        const float4 pv = __ldcs(&P4[y * Wq + tx]);

        float4 t = cs;                          // colsum for row y

        // advance window by 4 rows: add y+16..y+19, sub y-15..y-12
        #pragma unroll
        for (int k = 0; k < 4; ++k) {
            const int ra = y + 16 + k;
            const int rs = y - RAD + k;
            float4 aq, sq;
            if (!CLAMP) {
                aq = M4[ra * Wq + tx];
                sq = M4[rs * Wq + tx];
            } else {
                aq = (ra < H)  ? M4[ra * Wq + tx] : make_float4(0.f,0.f,0.f,0.f);
                sq = (rs >= 0) ? M4[rs * Wq + tx] : make_float4(0.f,0.f,0.f,0.f);
            }
            cs.x += aq.x - sq.x; cs.y += aq.y - sq.y;
            cs.z += aq.z - sq.z; cs.w += aq.w - sq.w;
        }

        // intra-thread prefix over 4 owned columns
        float p0 = t.x, p1 = p0 + t.y, p2 = p1 + t.z, p3 = p2 + t.w;

        // warp-inclusive scan of thread totals (one 128-col segment)
        float sinc = p3;
        #pragma unroll
        for (int off = 1; off < 32; off <<= 1) {
            float u = __shfl_up_sync(0xffffffffu, sinc, off);
            if (lane >= off) sinc += u;
        }
        float o = sinc - p3;                   // exclusive offset in segment
        if (lane == 31) sWT[sb][wrow] = sinc;
        __syncthreads();

        // add cross-segment offset -> store GLOBAL prefix quad
        {
            float4 tt = *(const float4*)sWT[sb];
            if (wrow > 0) o += tt.x;
            if (wrow > 1) o += tt.y;
            if (wrow > 2) o += tt.z;
        }
        float g3 = p3 + o;
        *(float4*)&sP[sb][16 + xb] = make_float4(p0 + o, p1 + o, p2 + o, g3);
        if (tx == 127) {                       // right pad = P(511)
            float4 pad = make_float4(g3, g3, g3, g3);
            *(float4*)&sP[sb][528] = pad; *(float4*)&sP[sb][532] = pad;
            *(float4*)&sP[sb][536] = pad; *(float4*)&sP[sb][540] = pad;
        }
        __syncthreads();

        // box(x) = P(x+15) - P(x-16): all aligned LDS.128
        float4 loq = *(const float4*)&sP[sb][xb];        // P(x-16), left pad=0
        float4 q1  = *(const float4*)&sP[sb][28 + xb];
        float4 q2  = *(const float4*)&sP[sb][32 + xb];

        pixel_math(q1.w - loq.x, m.x, pv.x, aw, ab, ai);
        pixel_math(q2.x - loq.y, m.y, pv.y, aw, ab, ai);
        pixel_math(q2.y - loq.z, m.z, pv.z, aw, ab, ai);
        pixel_math(q2.z - loq.w, m.w, pv.w, aw, ab, ai);
        // no trailing barrier: double buffer + next iteration's barriers
        // order the WAR on this buffer.
    }
}

__global__ __launch_bounds__(512, 2)
void fused_kernel(const float* __restrict__ pred,
                  const float* __restrict__ mask,
                  float* __restrict__ out) {
    __shared__ float sP[8][544];               // [buf*4+ty][16 pad|512|16 pad]
    __shared__ __align__(16) float sWT[8][4];  // per-segment totals
    __shared__ float red[3][16];
    __shared__ float fin[64];
    __shared__ int   s_last;

    const int tid  = threadIdx.x;
    const int lane = tid & 31;
    const int tx   = tid & 127;
    const int ty   = tid >> 7;
    const int wrow = tx >> 5;
    const int xb   = tx << 2;
    const int img  = blockIdx.y;
    const int y0   = blockIdx.x * STRIP;

    const float4* M4 = (const float4*)(mask + (size_t)img * W * H);
    const float4* P4 = (const float4*)(pred + (size_t)img * W * H);

    // zero left pads (indices 0..15 of all 8 rows); published by barrier1(it0)
    if (tid < 128) sP[tid >> 4][tid & 15] = 0.0f;

    float aw = 0.f, ab = 0.f, ai = 0.f;
    if (blockIdx.x == 0 || blockIdx.x == NSTRIP - 1)
        run_strip<true >(M4, P4, y0, tx, ty, lane, wrow, xb, sP, sWT, aw, ab, ai);
    else
        run_strip<false>(M4, P4, y0, tx, ty, lane, wrow, xb, sP, sWT, aw, ab, ai);

    // ---- block reduction of (aw, ab, ai) ----
    #pragma unroll
    for (int off = 16; off > 0; off >>= 1) {
        aw += __shfl_down_sync(0xffffffffu, aw, off);
        ab += __shfl_down_sync(0xffffffffu, ab, off);
        ai += __shfl_down_sync(0xffffffffu, ai, off);
    }
    const int wid = tid >> 5;
    if (lane == 0) { red[0][wid] = aw; red[1][wid] = ab; red[2][wid] = ai; }
    __syncthreads();
    if (wid == 0) {
        float a = (lane < 16) ? red[0][lane] : 0.0f;
        float b = (lane < 16) ? red[1][lane] : 0.0f;
        float c = (lane < 16) ? red[2][lane] : 0.0f;
        #pragma unroll
        for (int off = 8; off > 0; off >>= 1) {
            a += __shfl_down_sync(0xffffffffu, a, off);
            b += __shfl_down_sync(0xffffffffu, b, off);
            c += __shfl_down_sync(0xffffffffu, c, off);
        }
        if (lane == 0) {
            int bid = img * NSTRIP + blockIdx.x;
            g_part[bid * 3 + 0] = a;
            g_part[bid * 3 + 1] = b;
            g_part[bid * 3 + 2] = c;
            __threadfence();
            int prev = atomicAdd(&g_count, 1);
            s_last = (prev == NBLK - 1) ? 1 : 0;
        }
    }
    __syncthreads();

    // ---- last finished block computes the final scalar ----
    if (s_last) {
        if (tid < IMGS) {
            float w = 0.f, b = 0.f, u = 0.f;
            #pragma unroll
            for (int s = 0; s < NSTRIP; ++s) {
                int e2 = (tid * NSTRIP + s) * 3;
                w += g_part[e2 + 0];
                b += g_part[e2 + 1];
                u += g_part[e2 + 2];
            }
            fin[tid] = (b + u) / w;
        }
        __syncthreads();
        #pragma unroll
        for (int off = 32; off > 0; off >>= 1) {
            if (tid < off) fin[tid] += fin[tid + off];
            __syncthreads();
        }
        if (tid == 0) {
            out[0] = fin[0] * (1.0f / 64.0f);
            g_count = 0;                       // reset for next graph replay
        }
    }
}

extern "C" void kernel_launch(void* const* d_in, const int* in_sizes, int n_in,
                              void* d_out, int out_size) {
    const float* pred = (const float*)d_in[0];
    const float* mask = (const float*)d_in[1];
    float* out = (float*)d_out;

    dim3 grid(NSTRIP, IMGS);                  // 8 x 64 = 512 blocks
    fused_kernel<<<grid, W>>>(pred, mask, out);
}